// round 13
// baseline (speedup 1.0000x reference)
#include <cuda_runtime.h>
#include <cstdint>

// Math after collapse (verified, rel_err ~9e-7):
//   attn == 1/H exactly (softmax over an exactly-broadcast head axis)
//   sv[b,j]  = <sum_q v[b,q,:], Wv[j,:]> + Sq*bv[j]
//   row[b,d] = (1/H) * <sv[b,:], Wb[d,:]> + bb[d]
//   out[s,b,d] = row[b,d]  for all s
// Phase-1 decomposition: block x = (b, d-chunk c1 of 32 floats, q-quarter qh).
// Each block sums 256 q-rows of its 32-float slice, projects against the 8 KB
// Wv slice: svp2[qh,c1,b][j] = <vsum_slice_part, Wv[j, slice]>.
// sv[b,j] = Sq*bv[j] + sum over all 128 (qh,c1) contributions.
static constexpr int B  = 4;
static constexpr int SQ = 1024;
static constexpr int SK = 1024;
static constexpr int D  = 1024;
static constexpr int DH = 64;
static constexpr int H  = 16;

static constexpr int NC = 32;              // d-chunks of 32 floats
static constexpr int QH = 4;               // q-quarters (256 rows each)
static constexpr int NB = B * NC * QH;     // 512 blocks, all co-resident
static constexpr int ROW_F4 = B * D / 4;   // 1024 float4 per output tile (16 KB)
// Phase 2: block x owns output slice s = x & 31 (128 floats of the tile) and
// tile-group g = x >> 5 (64 tiles each; 16 groups x 64 = 1024 tiles).

// Scratch (__device__ globals; no allocation allowed)
__device__ float g_svp2[QH * NC * B * DH]; // 128 KB: projected partials
__device__ unsigned long long g_tick;      // monotonic ticket counter (never reset)

__device__ __forceinline__ float ldcg1(const float* p) {
    float r;
    asm volatile("ld.global.cg.f32 %0, [%1];" : "=f"(r) : "l"(p));
    return r;
}
__device__ __forceinline__ unsigned long long ld_acq(const unsigned long long* p) {
    unsigned long long v;
    asm volatile("ld.global.acquire.gpu.u64 %0, [%1];" : "=l"(v) : "l"(p));
    return v;
}

// ---------------------------------------------------------------------------
// One persistent kernel, 512 blocks x 256 threads (resource limits give >=6
// blocks/SM; only 4 needed for full co-residency -> grid sync is safe).
// ---------------------------------------------------------------------------
__global__ void __launch_bounds__(256)
fused_kernel(const float* __restrict__ v,
             const float* __restrict__ Wv, const float* __restrict__ bv,
             const float* __restrict__ Wb, const float* __restrict__ bb,
             float4* __restrict__ out4) {
    __shared__ float4 sred[256];      // 4 KB: stage-0 partials [qg(32)][sl(8)]
    __shared__ float4 sred2[64];      // 1 KB: stage-1 partials [g2(8)][sl(8)]
    __shared__ float  s_v[32];        // this block's q-quarter vsum slice
    __shared__ float  s_svp[4][DH];   // phase-2 partial sv sums
    __shared__ float  s_sv[DH];
    __shared__ float  s_slice[128];   // 512 B: this block's row slice
    __shared__ unsigned long long s_ticket;

    const int x = blockIdx.x;
    const int t = threadIdx.x;
    const int warp = t >> 5, lane = t & 31;

    // ---------------- phase 1: sliced partial column-sum + projection ------
    {
        const int b  = x & 3;
        const int c1 = (x >> 2) & 31;         // d-chunk, d0 = c1*32
        const int qh = x >> 7;                // q-quarter
        const int sl = t & 7;                 // float4 slot in slice
        const int qg = t >> 3;                // 0..31 q-group
        const float* vb = v + (size_t)b * SQ * D + c1 * 32 + sl * 4;

        float4 acc = make_float4(0.f, 0.f, 0.f, 0.f);
#pragma unroll
        for (int r = 0; r < 8; ++r) {
            const float4 xv = *reinterpret_cast<const float4*>(
                vb + (size_t)(qh * 256 + qg + r * 32) * D);
            acc.x += xv.x; acc.y += xv.y; acc.z += xv.z; acc.w += xv.w;
        }
        sred[t] = acc;                        // [qg][sl]
        __syncthreads();

        if (t < 64) {                         // fold 32 q-groups -> 8
            const int s2 = t & 7, g2 = t >> 3;
            float4 s = make_float4(0.f, 0.f, 0.f, 0.f);
#pragma unroll
            for (int i = 0; i < 4; ++i) {
                float4 a = sred[(g2 * 4 + i) * 8 + s2];
                s.x += a.x; s.y += a.y; s.z += a.z; s.w += a.w;
            }
            sred2[g2 * 8 + s2] = s;
        }
        __syncthreads();
        if (t < 8) {                          // finish (fixed order)
            float4 s = make_float4(0.f, 0.f, 0.f, 0.f);
#pragma unroll
            for (int g2 = 0; g2 < 8; ++g2) {
                float4 a = sred2[g2 * 8 + t];
                s.x += a.x; s.y += a.y; s.z += a.z; s.w += a.w;
            }
            reinterpret_cast<float4*>(s_v)[t] = s;
        }
        __syncthreads();

        // projection: 8 warps x 8 j's; lane l holds slice element l.
        const float a = s_v[lane];
#pragma unroll
        for (int jj = 0; jj < 8; ++jj) {
            const int j = warp * 8 + jj;
            float s = a * __ldg(&Wv[(size_t)j * D + c1 * 32 + lane]);
#pragma unroll
            for (int o = 16; o > 0; o >>= 1) s += __shfl_xor_sync(0xFFFFFFFFu, s, o);
            if (lane == 0) g_svp2[((qh * NC + c1) * B + b) * DH + j] = s;
        }
    }

    // ---------------- single grid sync (replay-safe tickets) ----------------
    __syncthreads();
    if (t == 0) {
        __threadfence();                                  // release svp2 writes
        s_ticket = atomicAdd(&g_tick, 1ULL);
    }
    __syncthreads();
    const unsigned long long target = (s_ticket / NB + 1ULL) * NB;
    if (t == 0) {
        while (ld_acq(&g_tick) < target) __nanosleep(32);
    }
    __syncthreads();                                      // acquire for all threads

    // ---------------- phase 2: block-local slice compute + stores ----------
    const int s  = x & 31;            // output slice: tile floats [s*128, +128)
    const int sb = s >> 3;            // batch of this slice
    const int g  = x >> 5;            // tile group: tiles [g*64, g*64+64)

    // sv[sb][j]: 4-way split over the 128 contributions, fixed-order combine.
    {
        const int j = t & 63, p = t >> 6;
        float sum = 0.f;
#pragma unroll
        for (int cc = p; cc < QH * NC; cc += 4)
            sum += ldcg1(&g_svp2[(cc * B + sb) * DH + j]);
        s_svp[p][j] = sum;
    }
    __syncthreads();
    if (t < DH)
        s_sv[t] = (float)SQ * __ldg(&bv[t])
                + ((s_svp[0][t] + s_svp[1][t]) + (s_svp[2][t] + s_svp[3][t]));
    __syncthreads();

    // row slice: d = (s&7)*128 + t for t < 128
    if (t < 128) {
        const int d = (s & 7) * 128 + t;
        const float4* wb = reinterpret_cast<const float4*>(Wb + (size_t)d * DH);
        float acc = 0.f;
#pragma unroll
        for (int j4 = 0; j4 < DH / 4; ++j4) {
            float4 w = __ldg(&wb[j4]);
            acc += s_sv[j4 * 4 + 0] * w.x + s_sv[j4 * 4 + 1] * w.y
                 + s_sv[j4 * 4 + 2] * w.z + s_sv[j4 * 4 + 3] * w.w;
        }
        s_slice[t] = acc * (1.0f / (float)H) + __ldg(&bb[d]);
    }
    __syncthreads();

    // stores: 8 warps x 8 tiles each; per-tile a 512B-contiguous warp store.
    {
        const float4 val = reinterpret_cast<const float4*>(s_slice)[lane];
        const int tile0 = g * 64 + warp * 8;
        float4* obase = out4 + (size_t)tile0 * ROW_F4 + s * 32 + lane;
#pragma unroll
        for (int r = 0; r < 8; ++r)
            obase[r * ROW_F4] = val;
    }
}

extern "C" void kernel_launch(void* const* d_in, const int* in_sizes, int n_in,
                              void* d_out, int out_size) {
    // Inputs: 0=q 1=k 2=h 3=w 4=v 5=Wq 6=bq 7=Wk 8=bk 9=Wv 10=bv 11=Wb 12=bb
    const float* v  = (const float*)d_in[4];
    const float* Wv = (const float*)d_in[9];
    const float* bv = (const float*)d_in[10];
    const float* Wb = (const float*)d_in[11];
    const float* bb = (const float*)d_in[12];

    fused_kernel<<<NB, 256>>>(v, Wv, bv, Wb, bb, (float4*)d_out);
}

// round 15
// speedup vs baseline: 1.3158x; 1.3158x over previous
#include <cuda_runtime.h>
#include <cstdint>

// Math after collapse (verified, rel_err ~9e-7):
//   attn == 1/H exactly (softmax over an exactly-broadcast head axis)
//   sv[b,j]  = <sum_q v[b,q,:], Wv[j,:]> + Sq*bv[j]
//   row[b,d] = (1/H) * <sv[b,:], Wb[d,:]> + bb[d]
//   out[s,b,d] = row[b,d]  for all s
// D-sliced phase 1 (round-11 winner): block x owns (b = x&3, d-slice
// [c1*32, c1*32+32), c1 = x>>2); sums its slice over ALL q; projects against
// the 8 KB Wv slice. sv[b,j] = Sq*bv[j] + sum of 32 slice contributions.
static constexpr int B  = 4;
static constexpr int SQ = 1024;
static constexpr int SK = 1024;
static constexpr int D  = 1024;
static constexpr int DH = 64;
static constexpr int H  = 16;

static constexpr int NC = 32;             // d-chunks of 32 floats
static constexpr int NB = B * NC;         // 128 blocks — single co-resident wave

static constexpr int ROW_F4 = B * D / 4;  // 1024 float4 per output tile (16 KB)
static constexpr int SKU = SK;            // (silence unused warnings) 1024 tiles
// Output slice decomposition: 32 slices x 128 floats; block x owns slice
// s = x & 31 and tile-group g = x >> 5 (256 tiles each).

// Scratch (__device__ globals; no allocation allowed)
__device__ float g_svp2[NB * DH];         // 32 KB: per-block projected partials
__device__ unsigned long long g_tick;     // monotonic ticket counter (never reset)

__device__ __forceinline__ float ldcg1(const float* p) {
    float r;
    asm volatile("ld.global.cg.f32 %0, [%1];" : "=f"(r) : "l"(p));
    return r;
}
__device__ __forceinline__ unsigned long long ld_acq(const unsigned long long* p) {
    unsigned long long v;
    asm volatile("ld.global.acquire.gpu.u64 %0, [%1];" : "=l"(v) : "l"(p));
    return v;
}

// ---------------------------------------------------------------------------
// One persistent kernel, 128 blocks x 1024 threads (co-resident wave).
//  phase 1: D-sliced v column-sum (full q) + tiny Wv-slice projection
//           -> g_svp2[x][64]
//  PRE-SYNC: prefetch this block's Wb slice into REGISTERS (2 float4/thread)
//            + bv + bb slice into small smem buffers
//  single replay-safe grid sync (monotonic ticket counter)
//  phase 2: sv from svp2 (1 MB grid-wide); row slice from register Wb via
//           8-lane shuffle dots; store slice into this block's 256 tiles.
// ---------------------------------------------------------------------------
__global__ void __launch_bounds__(1024)
fused_kernel(const float* __restrict__ v,
             const float* __restrict__ Wv, const float* __restrict__ bv,
             const float* __restrict__ Wb, const float* __restrict__ bb,
             float4* __restrict__ out4) {
    __shared__ float4 sred[1024];     // 16 KB: stage-0 partials
    __shared__ float4 sred2[256];     // 4 KB: stage-1 partials
    __shared__ float  s_v[32];        // this block's complete vsum slice
    __shared__ float  s_bv[DH];       // 256 B
    __shared__ float  s_bb[128];      // 512 B
    __shared__ float  s_sv[DH];       // 256 B
    __shared__ float  s_slice[128];   // 512 B: this block's row slice
    __shared__ unsigned long long s_ticket;

    const int x = blockIdx.x;
    const int t = threadIdx.x;
    const int b  = x & 3;
    const int c1 = x >> 2;            // d-chunk (32 floats), d0v = c1*32

    // phase-2 identity (needed early for prefetch)
    const int s  = x & 31;            // output slice: tile floats [s*128, +128)
    const int sb = s >> 3;            // batch of this slice
    const int g  = x >> 5;            // tile group: tiles [g*256, +256)
    const int d0 = (s & 7) * 128;     // slice's d-range start

    // Wb register prefetch mapping: row = t>>3 (0..127), sub = t&7 (j-segment)
    const int wrow = t >> 3, wsub = t & 7;

    // ---------------- phase 1: D-sliced column-sum over all q --------------
    {
        const int sl = t & 7;         // float4 slot in the 32-float slice
        const int qg = t >> 3;        // 0..127 q-group
        const float* vb = v + (size_t)b * SQ * D + c1 * 32 + sl * 4;

        float4 acc = make_float4(0.f, 0.f, 0.f, 0.f);
#pragma unroll
        for (int r = 0; r < 8; ++r) {
            const float4 xv = *reinterpret_cast<const float4*>(vb + (size_t)(qg + r * 128) * D);
            acc.x += xv.x; acc.y += xv.y; acc.z += xv.z; acc.w += xv.w;
        }
        sred[t] = acc;                // [qg][sl]
        __syncthreads();

        // stage 1: 256 threads fold 128 q-groups -> 32 groups
        if (t < 256) {
            const int s2 = t & 7, g2 = t >> 3;    // g2 in 0..31
            float4 sm = make_float4(0.f, 0.f, 0.f, 0.f);
#pragma unroll
            for (int i = 0; i < 4; ++i) {
                float4 a = sred[(g2 * 4 + i) * 8 + s2];
                sm.x += a.x; sm.y += a.y; sm.z += a.z; sm.w += a.w;
            }
            sred2[g2 * 8 + s2] = sm;
        }
        __syncthreads();

        // stage 2: 8 threads finish (fixed order), write vsum slice
        if (t < 8) {
            float4 sm = make_float4(0.f, 0.f, 0.f, 0.f);
#pragma unroll
            for (int g2 = 0; g2 < 32; ++g2) {
                float4 a = sred2[g2 * 8 + t];
                sm.x += a.x; sm.y += a.y; sm.z += a.z; sm.w += a.w;
            }
            reinterpret_cast<float4*>(s_v)[t] = sm;
        }
        __syncthreads();

        // projection: svp2[x][j] = <s_v, Wv[j, c1*32:+32]>
        // 32 warps x 2 j's each; lane l covers slice element l.
        const int warp = t >> 5, lane = t & 31;
        const float a = s_v[lane];
#pragma unroll
        for (int jj = 0; jj < 2; ++jj) {
            const int j = warp * 2 + jj;
            float sm = a * __ldg(&Wv[(size_t)j * D + c1 * 32 + lane]);
#pragma unroll
            for (int o = 16; o > 0; o >>= 1) sm += __shfl_xor_sync(0xFFFFFFFFu, sm, o);
            if (lane == 0) g_svp2[(c1 * B + b) * DH + j] = sm;
        }
    }

    // ------------- pre-sync prefetch (independent of barrier) --------------
    // Wb slice row (d0 + wrow), segment wsub: float4's wsub*2 and wsub*2+1.
    float4 wreg0, wreg1;
    {
        const float4* wbr = reinterpret_cast<const float4*>(Wb + (size_t)(d0 + wrow) * DH);
        wreg0 = __ldg(&wbr[wsub * 2 + 0]);
        wreg1 = __ldg(&wbr[wsub * 2 + 1]);
        if (t < DH)  s_bv[t] = __ldg(&bv[t]);
        if (t >= 512 && t < 640) s_bb[t - 512] = __ldg(&bb[d0 + (t - 512)]);
    }

    // ---------------- single grid sync (replay-safe tickets) ----------------
    __syncthreads();
    if (t == 0) {
        __threadfence();                                  // release svp2 writes
        s_ticket = atomicAdd(&g_tick, 1ULL);
    }
    __syncthreads();
    const unsigned long long target = (s_ticket / NB + 1ULL) * NB;
    if (t == 0) {
        while (ld_acq(&g_tick) < target) __nanosleep(32);
    }
    __syncthreads();                                      // acquire for all threads

    // ---------------- phase 2: block-local slice compute + stores ----------
    // sv[sb][j] for j = t < 64 (fixed-order sum over the 32 chunk blocks)
    if (t < DH) {
        float sum = (float)SQ * s_bv[t];
#pragma unroll
        for (int cc = 0; cc < NC; ++cc)
            sum += ldcg1(&g_svp2[(cc * B + sb) * DH + t]);
        s_sv[t] = sum;
    }
    __syncthreads();

    // row slice: 8 threads per d; thread covers j = wsub*8 .. wsub*8+7.
    {
        const int j0 = wsub * 8;
        float acc = s_sv[j0 + 0] * wreg0.x + s_sv[j0 + 1] * wreg0.y
                  + s_sv[j0 + 2] * wreg0.z + s_sv[j0 + 3] * wreg0.w
                  + s_sv[j0 + 4] * wreg1.x + s_sv[j0 + 5] * wreg1.y
                  + s_sv[j0 + 6] * wreg1.z + s_sv[j0 + 7] * wreg1.w;
        // fold the 8 lanes of this row (lanes wsub=0..7 are adjacent)
#pragma unroll
        for (int o = 1; o < 8; o <<= 1) acc += __shfl_xor_sync(0xFFFFFFFFu, acc, o);
        if (wsub == 0) s_slice[wrow] = acc * (1.0f / (float)H) + s_bb[wrow];
    }
    __syncthreads();

    // stores: 32 warps x 8 tiles each; per-tile a 512B-contiguous warp store.
    {
        const int warp = t >> 5, lane = t & 31;
        const float4 val = reinterpret_cast<const float4*>(s_slice)[lane];
        const int tile0 = g * 256 + warp * 8;
        float4* obase = out4 + (size_t)tile0 * ROW_F4 + s * 32 + lane;
#pragma unroll
        for (int r = 0; r < 8; ++r)
            obase[r * ROW_F4] = val;
    }
    (void)SKU;
}

extern "C" void kernel_launch(void* const* d_in, const int* in_sizes, int n_in,
                              void* d_out, int out_size) {
    // Inputs: 0=q 1=k 2=h 3=w 4=v 5=Wq 6=bq 7=Wk 8=bk 9=Wv 10=bv 11=Wb 12=bb
    const float* v  = (const float*)d_in[4];
    const float* Wv = (const float*)d_in[9];
    const float* bv = (const float*)d_in[10];
    const float* Wb = (const float*)d_in[11];
    const float* bb = (const float*)d_in[12];

    fused_kernel<<<NB, 1024>>>(v, Wv, bv, Wb, bb, (float4*)d_out);
}